// round 13
// baseline (speedup 1.0000x reference)
#include <cuda_runtime.h>
#include <cuda_bf16.h>
#include <math.h>
#include <stdint.h>

// Problem constants
#define BB 2
#define SS 2048
#define DD 1024
#define HH 16
#define DKK 64
#define MM (BB*SS)            // 4096 rows for projections

// ---------------------------------------------------------------------------
// Scratch (device globals: allocation-free)
// ---------------------------------------------------------------------------
__device__ __nv_bfloat16 g_Ahi[3][MM*DD];   // A hi (q,k,v inputs; slot0 reused for attn-out)
__device__ __nv_bfloat16 g_Alo[3][MM*DD];   // A lo
__device__ __nv_bfloat16 g_Wthi[4][DD*DD];  // W^T hi [N,K] (q,k,v,o)
__device__ __nv_bfloat16 g_Wtlo[4][DD*DD];  // W^T lo

__device__ __nv_bfloat16 g_Pqhi[BB*HH*SS*DKK];  // projected Q hi [bh][s][dk]
__device__ __nv_bfloat16 g_Pqlo[BB*HH*SS*DKK];
__device__ __nv_bfloat16 g_Pkhi[BB*HH*SS*DKK];  // projected K hi [bh][s][dk]
__device__ __nv_bfloat16 g_Pklo[BB*HH*SS*DKK];
__device__ __nv_bfloat16 g_Vthi[BB*HH*DKK*SS];  // projected V^T hi [bh][dk][s]
__device__ __nv_bfloat16 g_Vtlo[BB*HH*DKK*SS];

// ---------------------------------------------------------------------------
// Generic-PTX helpers (legal under compute_103): cp.async / ldmatrix / mma
// ---------------------------------------------------------------------------
static __device__ __forceinline__ uint32_t smem_u32(const void* p) {
    uint32_t a;
    asm("{ .reg .u64 t; cvta.to.shared.u64 t, %1; cvt.u32.u64 %0, t; }"
        : "=r"(a) : "l"(p));
    return a;
}

#define CP_ASYNC16(dst, src) \
    asm volatile("cp.async.cg.shared.global [%0], [%1], 16;" \
                 :: "r"(dst), "l"(src) : "memory")
#define CP_COMMIT() asm volatile("cp.async.commit_group;" ::: "memory")
#define CP_WAIT1()  asm volatile("cp.async.wait_group 1;" ::: "memory")
#define CP_WAIT0()  asm volatile("cp.async.wait_group 0;" ::: "memory")

#define LDSM_X4(r, addr) \
    asm volatile("ldmatrix.sync.aligned.m8n8.x4.shared.b16 {%0,%1,%2,%3}, [%4];" \
        : "=r"((r)[0]), "=r"((r)[1]), "=r"((r)[2]), "=r"((r)[3]) : "r"(addr))

#define MMA16816(c, a, b0, b1) \
    asm volatile("mma.sync.aligned.m16n8k16.row.col.f32.bf16.bf16.f32 " \
        "{%0,%1,%2,%3}, {%4,%5,%6,%7}, {%8,%9}, {%0,%1,%2,%3};" \
        : "+f"((c)[0]), "+f"((c)[1]), "+f"((c)[2]), "+f"((c)[3]) \
        : "r"((a)[0]), "r"((a)[1]), "r"((a)[2]), "r"((a)[3]), \
          "r"(b0), "r"(b1))

// pack two fp32 into bf16x2 hi, with bf16x2 residual lo
static __device__ __forceinline__ void split2(float a, float b,
                                              uint32_t& hi, uint32_t& lo) {
    __nv_bfloat162 h, l;
    h.x = __float2bfloat16_rn(a);
    h.y = __float2bfloat16_rn(b);
    l.x = __float2bfloat16_rn(a - __bfloat162float(h.x));
    l.y = __float2bfloat16_rn(b - __bfloat162float(h.y));
    hi = *(uint32_t*)&h;
    lo = *(uint32_t*)&l;
}

// ---------------------------------------------------------------------------
// fp32 -> bf16 hi/lo split of inputs q,k,v -> slots 0,1,2
// ---------------------------------------------------------------------------
__global__ __launch_bounds__(256)
void convA_kernel(const float* __restrict__ q,
                  const float* __restrict__ k,
                  const float* __restrict__ v)
{
    const int mat = blockIdx.y;
    const float* __restrict__ A = (mat == 0 ? q : mat == 1 ? k : v);
    const int i = blockIdx.x * 256 + threadIdx.x;        // float4 index
    float4 vv = ((const float4*)A)[i];

    uint32_t h01, l01, h23, l23;
    split2(vv.x, vv.y, h01, l01);
    split2(vv.z, vv.w, h23, l23);

    uint32_t* H = (uint32_t*)g_Ahi[mat];
    uint32_t* L = (uint32_t*)g_Alo[mat];
    H[2*i] = h01; H[2*i+1] = h23;
    L[2*i] = l01; L[2*i+1] = l23;
}

// ---------------------------------------------------------------------------
// W [K=DD, N=DD] fp32 -> transposed bf16 hi/lo [N, K]; blockIdx.z selects W.
// ---------------------------------------------------------------------------
__global__ __launch_bounds__(256)
void convW_kernel(const float* __restrict__ Wq, const float* __restrict__ Wk,
                  const float* __restrict__ Wv, const float* __restrict__ Wo)
{
    __shared__ float t[32][33];
    const int w = blockIdx.z;
    const float* __restrict__ W = (w == 0) ? Wq : (w == 1) ? Wk : (w == 2) ? Wv : Wo;
    const int n0 = blockIdx.x * 32;
    const int k0 = blockIdx.y * 32;
    const int tx = threadIdx.x;       // 0..31
    const int ty = threadIdx.y;       // 0..7

    #pragma unroll
    for (int i = 0; i < 4; i++)
        t[ty + 8*i][tx] = W[(size_t)(k0 + ty + 8*i) * DD + n0 + tx];
    __syncthreads();

    #pragma unroll
    for (int i = 0; i < 4; i++) {
        const int r = ty + 8*i;                  // local n
        const float v = t[tx][r];                // = W[k0+tx][n0+r]
        const int n = n0 + r, kk = k0 + tx;
        __nv_bfloat16 h = __float2bfloat16_rn(v);
        g_Wthi[w][(size_t)n * DD + kk] = h;
        g_Wtlo[w][(size_t)n * DD + kk] = __float2bfloat16_rn(v - __bfloat162float(h));
    }
}

// ---------------------------------------------------------------------------
// HMMA GEMM (mma.sync m16n8k16 bf16): C[M,N] = A @ W + bias, 3-term split.
// CTA 128x128, BK=32, 8 warps (2x4), warp tile 64x32.
// 3-stage cp.async pipeline, one __syncthreads per chunk.
// Runtime mode (mode_base + blockIdx.z):
//  0: -> g_Pqhi/lo  bf16 [bh][s][dk]
//  1: -> g_Pkhi/lo  bf16 [bh][s][dk]
//  2: -> g_Vthi/lo  bf16 [bh][dk][s]  (transposed for PV B-operand)
//  3: A slot 0 (attn out), W slot 3 -> fp32 row-major Cnat (d_out)
// ---------------------------------------------------------------------------
#define GBM 128
#define GBN 128
#define GBK 32
#define G_STG   32768                  // bytes per stage (4 tiles x 8KB)
#define G_AHI   0
#define G_ALO   8192
#define G_BHI   16384
#define G_BLO   24576
#define G_SMEM  (3*G_STG)              // 98304 (3-stage)
#define G_NCH   (DD/GBK)               // 32

// smem tile: 128 rows x 32 bf16 (64B row), XOR swizzle on 16B units.
// f(row) = (row>>1)&3 -> rows 0..7 cover all 8 (parity x unit) slots of
// addr mod 128 => ldmatrix 8-lane groups are bank-conflict-free.
static __device__ __forceinline__ uint32_t sw_off(int row, int ku) {
    return (uint32_t)(row * 64 + ((ku ^ ((row >> 1) & 3)) << 4));
}

__global__ __launch_bounds__(256, 2)
void mma_gemm_all(const float* __restrict__ bq, const float* __restrict__ bk,
                  const float* __restrict__ bv, const float* __restrict__ bo,
                  float* __restrict__ Cnat, int mode_base)
{
    extern __shared__ char sm[];
    const uint32_t sbase = smem_u32(sm);
    const int mode = mode_base + blockIdx.z;
    const float* __restrict__ bias =
        (mode == 0) ? bq : (mode == 1) ? bk : (mode == 2) ? bv : bo;
    const int tid  = threadIdx.x;
    const int wid  = tid >> 5;
    const int lane = tid & 31;
    const int m0 = blockIdx.x * GBM;
    const int n0 = blockIdx.y * GBN;
    const int wm = (wid >> 2) * 64;        // warp row origin (0/64)
    const int wn = (wid & 3) * 32;         // warp col origin (0/32/64/96)

    const int ASLOT = (mode == 3) ? 0 : mode;
    const __nv_bfloat16* __restrict__ Ahi = g_Ahi[ASLOT] + (size_t)m0 * DD;
    const __nv_bfloat16* __restrict__ Alo = g_Alo[ASLOT] + (size_t)m0 * DD;
    const __nv_bfloat16* __restrict__ Bhi = g_Wthi[mode] + (size_t)n0 * DD;
    const __nv_bfloat16* __restrict__ Blo = g_Wtlo[mode] + (size_t)n0 * DD;

    // per-thread copy coords: 2 (row,ku) pairs per tile
    const int r0 = tid >> 2,            ku0 = tid & 3;          // units 0..255
    const int r1 = (tid + 256) >> 2,    ku1 = (tid + 256) & 3;  // units 256..511

    float acc[4][4][4];
    #pragma unroll
    for (int i = 0; i < 4; i++)
        #pragma unroll
        for (int j = 0; j < 4; j++)
            #pragma unroll
            for (int r = 0; r < 4; r++) acc[i][j][r] = 0.0f;

    auto issue = [&](int c) {
        const int koff = c * GBK;
        const uint32_t dst = sbase + (uint32_t)(c % 3) * G_STG;
        const uint32_t o0 = sw_off(r0, ku0), o1 = sw_off(r1, ku1);
        const size_t g0 = (size_t)r0 * DD + koff + ku0 * 8;
        const size_t g1 = (size_t)r1 * DD + koff + ku1 * 8;
        CP_ASYNC16(dst + G_AHI + o0, Ahi + g0);
        CP_ASYNC16(dst + G_AHI + o1, Ahi + g1);
        CP_ASYNC16(dst + G_ALO + o0, Alo + g0);
        CP_ASYNC16(dst + G_ALO + o1, Alo + g1);
        CP_ASYNC16(dst + G_BHI + o0, Bhi + g0);
        CP_ASYNC16(dst + G_BHI + o1, Bhi + g1);
        CP_ASYNC16(dst + G_BLO + o0, Blo + g0);
        CP_ASYNC16(dst + G_BLO + o1, Blo + g1);
    };

    issue(0); CP_COMMIT();
    issue(1); CP_COMMIT();

    for (int c = 0; c < G_NCH; c++) {
        if (c + 1 < G_NCH) CP_WAIT1();   // chunk c landed (c+1 may be in flight)
        else               CP_WAIT0();
        __syncthreads();                 // all warps done with chunk c-1's buffer
        if (c + 2 < G_NCH) { issue(c + 2); CP_COMMIT(); }

        const uint32_t st = sbase + (uint32_t)(c % 3) * G_STG;

        #pragma unroll
        for (int s = 0; s < 2; s++) {          // two k16 steps per chunk
            const int lrow = lane & 15;
            const int lun  = s * 2 + (lane >> 4);

            uint32_t a_hi[4][4], a_lo[4][4];
            #pragma unroll
            for (int mf = 0; mf < 4; mf++) {
                const int row = wm + mf * 16 + lrow;
                const uint32_t ad = st + G_AHI + sw_off(row, lun);
                LDSM_X4(a_hi[mf], ad);
                LDSM_X4(a_lo[mf], ad + (G_ALO - G_AHI));
            }
            uint32_t bh[2][4], bl[2][4];
            #pragma unroll
            for (int g = 0; g < 2; g++) {
                const int row = wn + g * 16 + lrow;
                const uint32_t bd = st + G_BHI + sw_off(row, lun);
                LDSM_X4(bh[g], bd);
                LDSM_X4(bl[g], bd + (G_BLO - G_BHI));
            }

            #pragma unroll
            for (int mf = 0; mf < 4; mf++) {
                #pragma unroll
                for (int nf = 0; nf < 4; nf++) {
                    const int g = nf >> 1, h = nf & 1;
                    MMA16816(acc[mf][nf], a_hi[mf], bh[g][h], bh[g][h + 2]);
                    MMA16816(acc[mf][nf], a_hi[mf], bl[g][h], bl[g][h + 2]);
                    MMA16816(acc[mf][nf], a_lo[mf], bh[g][h], bh[g][h + 2]);
                }
            }
        }
    }

    // ---- epilogue ----
    #pragma unroll
    for (int mf = 0; mf < 4; mf++) {
        const int rA = m0 + wm + mf * 16 + (lane >> 2);  // rows rA, rA+8
        #pragma unroll
        for (int nf = 0; nf < 4; nf++) {
            const int col = n0 + wn + nf * 8 + (lane & 3) * 2;
            const float b0 = bias[col], b1 = bias[col + 1];
            const float f0 = acc[mf][nf][0] + b0, f1 = acc[mf][nf][1] + b1;
            const float f2 = acc[mf][nf][2] + b0, f3 = acc[mf][nf][3] + b1;
            if (mode == 3) {
                *(float2*)&Cnat[(size_t)rA * DD + col] = make_float2(f0, f1);
                *(float2*)&Cnat[(size_t)(rA + 8) * DD + col] = make_float2(f2, f3);
            } else {
                const int h  = col >> 6;
                const int dk = col & 63;
                if (mode == 2) {
                    // transposed scatter: [bh][dk][s]
                    #pragma unroll
                    for (int e = 0; e < 4; e++) {
                        const float f = (e == 0) ? f0 : (e == 1) ? f1 : (e == 2) ? f2 : f3;
                        const int rr = rA + ((e >= 2) ? 8 : 0);
                        const int dkk = dk + (e & 1);
                        const int b = rr >> 11, sq = rr & 2047;
                        const size_t idx = (((size_t)((b * HH + h) * DKK + dkk)) * SS) + sq;
                        __nv_bfloat16 hv = __float2bfloat16_rn(f);
                        g_Vthi[idx] = hv;
                        g_Vtlo[idx] = __float2bfloat16_rn(f - __bfloat162float(hv));
                    }
                } else {
                    __nv_bfloat16* Dh = (mode == 0) ? g_Pqhi : g_Pkhi;
                    __nv_bfloat16* Dl = (mode == 0) ? g_Pqlo : g_Pklo;
                    uint32_t hi, lo;
                    {
                        const int b = rA >> 11, sq = rA & 2047;
                        const size_t idx = (((size_t)(b * HH + h)) * SS + sq) * DKK + dk;
                        split2(f0, f1, hi, lo);
                        *(uint32_t*)&Dh[idx] = hi;
                        *(uint32_t*)&Dl[idx] = lo;
                    }
                    {
                        const int r2 = rA + 8;
                        const int b = r2 >> 11, sq = r2 & 2047;
                        const size_t idx = (((size_t)(b * HH + h)) * SS + sq) * DKK + dk;
                        split2(f2, f3, hi, lo);
                        *(uint32_t*)&Dh[idx] = hi;
                        *(uint32_t*)&Dl[idx] = lo;
                    }
                }
            }
        }
    }
}

// ---------------------------------------------------------------------------
// Tensor-core flash attention (causal), 3-term bf16 split on QK^T and PV.
// grid (S/128, B*H), 256 threads (8 warps x 16 q-rows).
// R13: reg-capped to 128 (2 CTAs/SM) + reversed q-tile order (LPT schedule).
// ---------------------------------------------------------------------------
#define AS_QHI   0
#define AS_QLO   16384
#define AS_STG   32768
#define AS_STGSZ 32768          // KHI 0 | KLO 8192 | VHI 16384 | VLO 24576
#define ATTN_SMEM (AS_STG + 2*AS_STGSZ)   // 98304

#define C_SCALE 0.180336880f    // 0.125 * log2(e)

// 128B rows (64 bf16): XOR swizzle over 8 units (conflict-free)
static __device__ __forceinline__ uint32_t sw128(int row, int u) {
    return (uint32_t)(row * 128 + ((u ^ (row & 7)) << 4));
}

__global__ __launch_bounds__(256, 2)
void attn_tc()
{
    extern __shared__ char sm[];
    const uint32_t sb = smem_u32(sm);
    const int tid  = threadIdx.x;
    const int warp = tid >> 5;
    const int lane = tid & 31;
    const int lrow = lane & 15, lhalf = lane >> 4;
    const int g = lane >> 2,  t4 = lane & 3;
    // Reversed q-tile order: heavy CTAs (large q0, more k-tiles) first.
    const int q0 = (gridDim.x - 1 - blockIdx.x) * 128;
    const int bh = blockIdx.y;

    const __nv_bfloat16* __restrict__ Qhi = g_Pqhi + (size_t)bh * SS * DKK;
    const __nv_bfloat16* __restrict__ Qlo = g_Pqlo + (size_t)bh * SS * DKK;
    const __nv_bfloat16* __restrict__ Khi = g_Pkhi + (size_t)bh * SS * DKK;
    const __nv_bfloat16* __restrict__ Klo = g_Pklo + (size_t)bh * SS * DKK;
    const __nv_bfloat16* __restrict__ Vth = g_Vthi + (size_t)bh * DKK * SS;
    const __nv_bfloat16* __restrict__ Vtl = g_Vtlo + (size_t)bh * DKK * SS;

    // Q load (once): 128 rows x 8 units, hi+lo
    #pragma unroll
    for (int i = 0; i < 4; i++) {
        const int un = tid + i * 256;
        const int r = un >> 3, u = un & 7;
        const size_t go = (size_t)(q0 + r) * DKK + u * 8;
        CP_ASYNC16(sb + AS_QHI + sw128(r, u), Qhi + go);
        CP_ASYNC16(sb + AS_QLO + sw128(r, u), Qlo + go);
    }

    auto cpKV = [&](int t) {
        const int k0 = t * 64;
        const uint32_t st = sb + AS_STG + (uint32_t)(t & 1) * AS_STGSZ;
        #pragma unroll
        for (int i = 0; i < 2; i++) {
            const int un = tid + i * 256;     // 512 units (64 rows x 8)
            const int r = un >> 3, u = un & 7;
            CP_ASYNC16(st + 0     + sw128(r, u), Khi + (size_t)(k0 + r) * DKK + u * 8);
            CP_ASYNC16(st + 8192  + sw128(r, u), Klo + (size_t)(k0 + r) * DKK + u * 8);
            CP_ASYNC16(st + 16384 + sw128(r, u), Vth + (size_t)r * SS + k0 + u * 8);
            CP_ASYNC16(st + 24576 + sw128(r, u), Vtl + (size_t)r * SS + k0 + u * 8);
        }
    };

    float O[8][4];
    #pragma unroll
    for (int nf = 0; nf < 8; nf++)
        #pragma unroll
        for (int r = 0; r < 4; r++) O[nf][r] = 0.0f;
    float m0 = -1e30f, m8 = -1e30f, l0v = 0.0f, l8v = 0.0f;

    const int nkt = q0 / 64 + 2;

    cpKV(0);
    CP_COMMIT();

    for (int t = 0; t < nkt; t++) {
        if (t + 1 < nkt) { cpKV(t + 1); CP_COMMIT(); CP_WAIT1(); }
        else             { CP_WAIT0(); }
        __syncthreads();

        const uint32_t st = sb + AS_STG + (uint32_t)(t & 1) * AS_STGSZ;

        // ---- S = Q K^T (3-term) ----
        float sc[8][4];
        #pragma unroll
        for (int nf = 0; nf < 8; nf++)
            #pragma unroll
            for (int r = 0; r < 4; r++) sc[nf][r] = 0.0f;

        #pragma unroll
        for (int s = 0; s < 4; s++) {
            uint32_t aH[4], aL[4];
            const uint32_t qa = sb + AS_QHI + sw128(warp * 16 + lrow, 2 * s + lhalf);
            LDSM_X4(aH, qa);
            LDSM_X4(aL, qa + (AS_QLO - AS_QHI));
            uint32_t bH[4][4], bL[4][4];
            #pragma unroll
            for (int kg = 0; kg < 4; kg++) {
                const uint32_t ka = st + sw128(kg * 16 + lrow, 2 * s + lhalf);
                LDSM_X4(bH[kg], ka);
                LDSM_X4(bL[kg], ka + 8192);
            }
            #pragma unroll
            for (int nf = 0; nf < 8; nf++) {
                const int kg = nf >> 1, h = nf & 1;
                MMA16816(sc[nf], aH, bH[kg][h], bH[kg][h + 2]);
                MMA16816(sc[nf], aH, bL[kg][h], bL[kg][h + 2]);
                MMA16816(sc[nf], aL, bH[kg][h], bH[kg][h + 2]);
            }
        }

        // ---- causal mask (only last two tiles can cross diagonal) ----
        const int k0 = t * 64;
        if (k0 + 63 > q0) {
            const int r0g = q0 + warp * 16 + g;
            const int r8g = r0g + 8;
            #pragma unroll
            for (int nf = 0; nf < 8; nf++) {
                const int c0 = k0 + nf * 8 + t4 * 2;
                if (c0     > r0g) sc[nf][0] = -1e30f;
                if (c0 + 1 > r0g) sc[nf][1] = -1e30f;
                if (c0     > r8g) sc[nf][2] = -1e30f;
                if (c0 + 1 > r8g) sc[nf][3] = -1e30f;
            }
        }

        // ---- online softmax (rows g and g+8; reduce over 4 lanes) ----
        float mx0 = -1e30f, mx8 = -1e30f;
        #pragma unroll
        for (int nf = 0; nf < 8; nf++) {
            mx0 = fmaxf(mx0, fmaxf(sc[nf][0], sc[nf][1]));
            mx8 = fmaxf(mx8, fmaxf(sc[nf][2], sc[nf][3]));
        }
        mx0 = fmaxf(mx0, __shfl_xor_sync(0xffffffffu, mx0, 1));
        mx0 = fmaxf(mx0, __shfl_xor_sync(0xffffffffu, mx0, 2));
        mx8 = fmaxf(mx8, __shfl_xor_sync(0xffffffffu, mx8, 1));
        mx8 = fmaxf(mx8, __shfl_xor_sync(0xffffffffu, mx8, 2));

        const float mn0 = fmaxf(m0, mx0), mn8 = fmaxf(m8, mx8);
        const float al0 = exp2f((m0 - mn0) * C_SCALE);
        const float al8 = exp2f((m8 - mn8) * C_SCALE);

        float rs0 = 0.0f, rs8 = 0.0f;
        #pragma unroll
        for (int nf = 0; nf < 8; nf++) {
            sc[nf][0] = exp2f((sc[nf][0] - mn0) * C_SCALE);
            sc[nf][1] = exp2f((sc[nf][1] - mn0) * C_SCALE);
            sc[nf][2] = exp2f((sc[nf][2] - mn8) * C_SCALE);
            sc[nf][3] = exp2f((sc[nf][3] - mn8) * C_SCALE);
            rs0 += sc[nf][0] + sc[nf][1];
            rs8 += sc[nf][2] + sc[nf][3];
        }
        rs0 += __shfl_xor_sync(0xffffffffu, rs0, 1);
        rs0 += __shfl_xor_sync(0xffffffffu, rs0, 2);
        rs8 += __shfl_xor_sync(0xffffffffu, rs8, 1);
        rs8 += __shfl_xor_sync(0xffffffffu, rs8, 2);

        l0v = l0v * al0 + rs0;
        l8v = l8v * al8 + rs8;
        m0 = mn0; m8 = mn8;

        #pragma unroll
        for (int nf = 0; nf < 8; nf++) {
            O[nf][0] *= al0; O[nf][1] *= al0;
            O[nf][2] *= al8; O[nf][3] *= al8;
        }

        // ---- pack P into A-operand frags (hi/lo) ----
        uint32_t aPh[4][4], aPl[4][4];
        #pragma unroll
        for (int s = 0; s < 4; s++) {
            split2(sc[2*s][0],   sc[2*s][1],   aPh[s][0], aPl[s][0]);
            split2(sc[2*s][2],   sc[2*s][3],   aPh[s][1], aPl[s][1]);
            split2(sc[2*s+1][0], sc[2*s+1][1], aPh[s][2], aPl[s][2]);
            split2(sc[2*s+1][2], sc[2*s+1][3], aPh[s][3], aPl[s][3]);
        }

        // ---- O += P V (3-term) ----
        #pragma unroll
        for (int s = 0; s < 4; s++) {
            uint32_t vH[4][4], vL[4][4];
            #pragma unroll
            for (int vg = 0; vg < 4; vg++) {
                const uint32_t va = st + 16384 + sw128(vg * 16 + lrow, 2 * s + lhalf);
                LDSM_X4(vH[vg], va);
                LDSM_X4(vL[vg], va + 8192);
            }
            #pragma unroll
            for (int nf = 0; nf < 8; nf++) {
                const int vg = nf >> 1, h = nf & 1;
                MMA16816(O[nf], aPh[s], vH[vg][h], vH[vg][h + 2]);
                MMA16816(O[nf], aPh[s], vL[vg][h], vL[vg][h + 2]);
                MMA16816(O[nf], aPl[s], vH[vg][h], vH[vg][h + 2]);
            }
        }
        __syncthreads();
    }

    // ---- epilogue: O/l -> bf16 hi/lo into A slot 0 ----
    const float i0 = 1.0f / l0v, i8 = 1.0f / l8v;
    const int b = bh >> 4, h = bh & 15;
    const int s0 = q0 + warp * 16 + g;
    #pragma unroll
    for (int nf = 0; nf < 8; nf++) {
        const int n = h * 64 + nf * 8 + t4 * 2;
        uint32_t hi, lo;
        split2(O[nf][0] * i0, O[nf][1] * i0, hi, lo);
        size_t idx = ((size_t)b * SS + s0) * DD + n;
        *(uint32_t*)&g_Ahi[0][idx] = hi;
        *(uint32_t*)&g_Alo[0][idx] = lo;
        split2(O[nf][2] * i8, O[nf][3] * i8, hi, lo);
        idx = ((size_t)b * SS + s0 + 8) * DD + n;
        *(uint32_t*)&g_Ahi[0][idx] = hi;
        *(uint32_t*)&g_Alo[0][idx] = lo;
    }
}

// ---------------------------------------------------------------------------
// Launch
// ---------------------------------------------------------------------------
extern "C" void kernel_launch(void* const* d_in, const int* in_sizes, int n_in,
                              void* d_out, int out_size)
{
    const float* q  = (const float*)d_in[0];
    const float* k  = (const float*)d_in[1];
    const float* v  = (const float*)d_in[2];
    // d_in[3] = causal mask (structure known, not read)
    const float* Wq = (const float*)d_in[4];
    const float* bq = (const float*)d_in[5];
    const float* Wk = (const float*)d_in[6];
    const float* bk = (const float*)d_in[7];
    const float* Wv = (const float*)d_in[8];
    const float* bv = (const float*)d_in[9];
    const float* Wo = (const float*)d_in[10];
    const float* bo = (const float*)d_in[11];
    float* out = (float*)d_out;

    cudaFuncSetAttribute(attn_tc,
                         cudaFuncAttributeMaxDynamicSharedMemorySize, ATTN_SMEM);
    cudaFuncSetAttribute(mma_gemm_all,
                         cudaFuncAttributeMaxDynamicSharedMemorySize, G_SMEM);

    dim3 cgrid((MM * DD / 4) / 256, 3);               // (4096, 3)
    dim3 wgrid(DD / 32, DD / 32, 4);                  // (32, 32, 4)
    dim3 wblk(32, 8);

    convA_kernel<<<cgrid, 256>>>(q, k, v);            // q,k,v -> slots 0,1,2
    convW_kernel<<<wgrid, wblk>>>(Wq, Wk, Wv, Wo);    // all 4 W^T splits

    dim3 gqkv(MM / GBM, DD / GBN, 3);                 // (32, 8, 3) merged QKV
    mma_gemm_all<<<gqkv, 256, G_SMEM>>>(bq, bk, bv, bo, nullptr, 0);

    dim3 agrid(SS / 128, BB * HH);                    // (16, 32)
    attn_tc<<<agrid, 256, ATTN_SMEM>>>();

    dim3 gout(MM / GBM, DD / GBN, 1);                 // (32, 8, 1) Wo
    mma_gemm_all<<<gout, 256, G_SMEM>>>(bq, bk, bv, bo, out, 3);
}

// round 14
// speedup vs baseline: 1.0625x; 1.0625x over previous
#include <cuda_runtime.h>
#include <cuda_bf16.h>
#include <math.h>
#include <stdint.h>

// Problem constants
#define BB 2
#define SS 2048
#define DD 1024
#define HH 16
#define DKK 64
#define MM (BB*SS)            // 4096 rows for projections

// ---------------------------------------------------------------------------
// Scratch (device globals: allocation-free)
// ---------------------------------------------------------------------------
__device__ __nv_bfloat16 g_Ahi[3][MM*DD];   // A hi (q,k,v inputs; slot0 reused for attn-out)
__device__ __nv_bfloat16 g_Alo[3][MM*DD];   // A lo
__device__ __nv_bfloat16 g_Wthi[4][DD*DD];  // W^T hi [N,K] (q,k,v,o)
__device__ __nv_bfloat16 g_Wtlo[4][DD*DD];  // W^T lo

__device__ __nv_bfloat16 g_Pqhi[BB*HH*SS*DKK];  // projected Q hi [bh][s][dk]
__device__ __nv_bfloat16 g_Pqlo[BB*HH*SS*DKK];
__device__ __nv_bfloat16 g_Pkhi[BB*HH*SS*DKK];  // projected K hi [bh][s][dk]
__device__ __nv_bfloat16 g_Pklo[BB*HH*SS*DKK];
__device__ __nv_bfloat16 g_Vthi[BB*HH*DKK*SS];  // projected V^T hi [bh][dk][s]
__device__ __nv_bfloat16 g_Vtlo[BB*HH*DKK*SS];

// ---------------------------------------------------------------------------
// Generic-PTX helpers (legal under compute_103): cp.async / ldmatrix / mma
// ---------------------------------------------------------------------------
static __device__ __forceinline__ uint32_t smem_u32(const void* p) {
    uint32_t a;
    asm("{ .reg .u64 t; cvta.to.shared.u64 t, %1; cvt.u32.u64 %0, t; }"
        : "=r"(a) : "l"(p));
    return a;
}

#define CP_ASYNC16(dst, src) \
    asm volatile("cp.async.cg.shared.global [%0], [%1], 16;" \
                 :: "r"(dst), "l"(src) : "memory")
#define CP_COMMIT() asm volatile("cp.async.commit_group;" ::: "memory")
#define CP_WAIT1()  asm volatile("cp.async.wait_group 1;" ::: "memory")
#define CP_WAIT0()  asm volatile("cp.async.wait_group 0;" ::: "memory")

#define LDSM_X4(r, addr) \
    asm volatile("ldmatrix.sync.aligned.m8n8.x4.shared.b16 {%0,%1,%2,%3}, [%4];" \
        : "=r"((r)[0]), "=r"((r)[1]), "=r"((r)[2]), "=r"((r)[3]) : "r"(addr))

#define MMA16816(c, a, b0, b1) \
    asm volatile("mma.sync.aligned.m16n8k16.row.col.f32.bf16.bf16.f32 " \
        "{%0,%1,%2,%3}, {%4,%5,%6,%7}, {%8,%9}, {%0,%1,%2,%3};" \
        : "+f"((c)[0]), "+f"((c)[1]), "+f"((c)[2]), "+f"((c)[3]) \
        : "r"((a)[0]), "r"((a)[1]), "r"((a)[2]), "r"((a)[3]), \
          "r"(b0), "r"(b1))

// pack two fp32 into bf16x2 hi, with bf16x2 residual lo
static __device__ __forceinline__ void split2(float a, float b,
                                              uint32_t& hi, uint32_t& lo) {
    __nv_bfloat162 h, l;
    h.x = __float2bfloat16_rn(a);
    h.y = __float2bfloat16_rn(b);
    l.x = __float2bfloat16_rn(a - __bfloat162float(h.x));
    l.y = __float2bfloat16_rn(b - __bfloat162float(h.y));
    hi = *(uint32_t*)&h;
    lo = *(uint32_t*)&l;
}

// ---------------------------------------------------------------------------
// fp32 -> bf16 hi/lo split of inputs q,k,v -> slots 0,1,2
// ---------------------------------------------------------------------------
__global__ __launch_bounds__(256)
void convA_kernel(const float* __restrict__ q,
                  const float* __restrict__ k,
                  const float* __restrict__ v)
{
    const int mat = blockIdx.y;
    const float* __restrict__ A = (mat == 0 ? q : mat == 1 ? k : v);
    const int i = blockIdx.x * 256 + threadIdx.x;        // float4 index
    float4 vv = ((const float4*)A)[i];

    uint32_t h01, l01, h23, l23;
    split2(vv.x, vv.y, h01, l01);
    split2(vv.z, vv.w, h23, l23);

    uint32_t* H = (uint32_t*)g_Ahi[mat];
    uint32_t* L = (uint32_t*)g_Alo[mat];
    H[2*i] = h01; H[2*i+1] = h23;
    L[2*i] = l01; L[2*i+1] = l23;
}

// ---------------------------------------------------------------------------
// W [K=DD, N=DD] fp32 -> transposed bf16 hi/lo [N, K]; blockIdx.z selects W.
// ---------------------------------------------------------------------------
__global__ __launch_bounds__(256)
void convW_kernel(const float* __restrict__ Wq, const float* __restrict__ Wk,
                  const float* __restrict__ Wv, const float* __restrict__ Wo)
{
    __shared__ float t[32][33];
    const int w = blockIdx.z;
    const float* __restrict__ W = (w == 0) ? Wq : (w == 1) ? Wk : (w == 2) ? Wv : Wo;
    const int n0 = blockIdx.x * 32;
    const int k0 = blockIdx.y * 32;
    const int tx = threadIdx.x;       // 0..31
    const int ty = threadIdx.y;       // 0..7

    #pragma unroll
    for (int i = 0; i < 4; i++)
        t[ty + 8*i][tx] = W[(size_t)(k0 + ty + 8*i) * DD + n0 + tx];
    __syncthreads();

    #pragma unroll
    for (int i = 0; i < 4; i++) {
        const int r = ty + 8*i;                  // local n
        const float v = t[tx][r];                // = W[k0+tx][n0+r]
        const int n = n0 + r, kk = k0 + tx;
        __nv_bfloat16 h = __float2bfloat16_rn(v);
        g_Wthi[w][(size_t)n * DD + kk] = h;
        g_Wtlo[w][(size_t)n * DD + kk] = __float2bfloat16_rn(v - __bfloat162float(h));
    }
}

// ---------------------------------------------------------------------------
// HMMA GEMM (mma.sync m16n8k16 bf16): C[M,N] = A @ W + bias, 3-term split.
// CTA 128x128, BK=32, 8 warps (2x4), warp tile 64x32.
// 3-stage cp.async pipeline, one __syncthreads per chunk. (R12 config.)
// ---------------------------------------------------------------------------
#define GBM 128
#define GBN 128
#define GBK 32
#define G_STG   32768                  // bytes per stage (4 tiles x 8KB)
#define G_AHI   0
#define G_ALO   8192
#define G_BHI   16384
#define G_BLO   24576
#define G_SMEM  (3*G_STG)              // 98304 (3-stage)
#define G_NCH   (DD/GBK)               // 32

// smem tile: 128 rows x 32 bf16 (64B row), XOR swizzle on 16B units.
static __device__ __forceinline__ uint32_t sw_off(int row, int ku) {
    return (uint32_t)(row * 64 + ((ku ^ ((row >> 1) & 3)) << 4));
}

__global__ __launch_bounds__(256, 2)
void mma_gemm_all(const float* __restrict__ bq, const float* __restrict__ bk,
                  const float* __restrict__ bv, const float* __restrict__ bo,
                  float* __restrict__ Cnat, int mode_base)
{
    extern __shared__ char sm[];
    const uint32_t sbase = smem_u32(sm);
    const int mode = mode_base + blockIdx.z;
    const float* __restrict__ bias =
        (mode == 0) ? bq : (mode == 1) ? bk : (mode == 2) ? bv : bo;
    const int tid  = threadIdx.x;
    const int wid  = tid >> 5;
    const int lane = tid & 31;
    const int m0 = blockIdx.x * GBM;
    const int n0 = blockIdx.y * GBN;
    const int wm = (wid >> 2) * 64;        // warp row origin (0/64)
    const int wn = (wid & 3) * 32;         // warp col origin (0/32/64/96)

    const int ASLOT = (mode == 3) ? 0 : mode;
    const __nv_bfloat16* __restrict__ Ahi = g_Ahi[ASLOT] + (size_t)m0 * DD;
    const __nv_bfloat16* __restrict__ Alo = g_Alo[ASLOT] + (size_t)m0 * DD;
    const __nv_bfloat16* __restrict__ Bhi = g_Wthi[mode] + (size_t)n0 * DD;
    const __nv_bfloat16* __restrict__ Blo = g_Wtlo[mode] + (size_t)n0 * DD;

    const int r0 = tid >> 2,            ku0 = tid & 3;          // units 0..255
    const int r1 = (tid + 256) >> 2,    ku1 = (tid + 256) & 3;  // units 256..511

    float acc[4][4][4];
    #pragma unroll
    for (int i = 0; i < 4; i++)
        #pragma unroll
        for (int j = 0; j < 4; j++)
            #pragma unroll
            for (int r = 0; r < 4; r++) acc[i][j][r] = 0.0f;

    auto issue = [&](int c) {
        const int koff = c * GBK;
        const uint32_t dst = sbase + (uint32_t)(c % 3) * G_STG;
        const uint32_t o0 = sw_off(r0, ku0), o1 = sw_off(r1, ku1);
        const size_t g0 = (size_t)r0 * DD + koff + ku0 * 8;
        const size_t g1 = (size_t)r1 * DD + koff + ku1 * 8;
        CP_ASYNC16(dst + G_AHI + o0, Ahi + g0);
        CP_ASYNC16(dst + G_AHI + o1, Ahi + g1);
        CP_ASYNC16(dst + G_ALO + o0, Alo + g0);
        CP_ASYNC16(dst + G_ALO + o1, Alo + g1);
        CP_ASYNC16(dst + G_BHI + o0, Bhi + g0);
        CP_ASYNC16(dst + G_BHI + o1, Bhi + g1);
        CP_ASYNC16(dst + G_BLO + o0, Blo + g0);
        CP_ASYNC16(dst + G_BLO + o1, Blo + g1);
    };

    issue(0); CP_COMMIT();
    issue(1); CP_COMMIT();

    for (int c = 0; c < G_NCH; c++) {
        if (c + 1 < G_NCH) CP_WAIT1();
        else               CP_WAIT0();
        __syncthreads();
        if (c + 2 < G_NCH) { issue(c + 2); CP_COMMIT(); }

        const uint32_t st = sbase + (uint32_t)(c % 3) * G_STG;

        #pragma unroll
        for (int s = 0; s < 2; s++) {
            const int lrow = lane & 15;
            const int lun  = s * 2 + (lane >> 4);

            uint32_t a_hi[4][4], a_lo[4][4];
            #pragma unroll
            for (int mf = 0; mf < 4; mf++) {
                const int row = wm + mf * 16 + lrow;
                const uint32_t ad = st + G_AHI + sw_off(row, lun);
                LDSM_X4(a_hi[mf], ad);
                LDSM_X4(a_lo[mf], ad + (G_ALO - G_AHI));
            }
            uint32_t bh[2][4], bl[2][4];
            #pragma unroll
            for (int g = 0; g < 2; g++) {
                const int row = wn + g * 16 + lrow;
                const uint32_t bd = st + G_BHI + sw_off(row, lun);
                LDSM_X4(bh[g], bd);
                LDSM_X4(bl[g], bd + (G_BLO - G_BHI));
            }

            #pragma unroll
            for (int mf = 0; mf < 4; mf++) {
                #pragma unroll
                for (int nf = 0; nf < 4; nf++) {
                    const int g = nf >> 1, h = nf & 1;
                    MMA16816(acc[mf][nf], a_hi[mf], bh[g][h], bh[g][h + 2]);
                    MMA16816(acc[mf][nf], a_hi[mf], bl[g][h], bl[g][h + 2]);
                    MMA16816(acc[mf][nf], a_lo[mf], bh[g][h], bh[g][h + 2]);
                }
            }
        }
    }

    // ---- epilogue ----
    #pragma unroll
    for (int mf = 0; mf < 4; mf++) {
        const int rA = m0 + wm + mf * 16 + (lane >> 2);  // rows rA, rA+8
        #pragma unroll
        for (int nf = 0; nf < 4; nf++) {
            const int col = n0 + wn + nf * 8 + (lane & 3) * 2;
            const float b0 = bias[col], b1 = bias[col + 1];
            const float f0 = acc[mf][nf][0] + b0, f1 = acc[mf][nf][1] + b1;
            const float f2 = acc[mf][nf][2] + b0, f3 = acc[mf][nf][3] + b1;
            if (mode == 3) {
                *(float2*)&Cnat[(size_t)rA * DD + col] = make_float2(f0, f1);
                *(float2*)&Cnat[(size_t)(rA + 8) * DD + col] = make_float2(f2, f3);
            } else {
                const int h  = col >> 6;
                const int dk = col & 63;
                if (mode == 2) {
                    #pragma unroll
                    for (int e = 0; e < 4; e++) {
                        const float f = (e == 0) ? f0 : (e == 1) ? f1 : (e == 2) ? f2 : f3;
                        const int rr = rA + ((e >= 2) ? 8 : 0);
                        const int dkk = dk + (e & 1);
                        const int b = rr >> 11, sq = rr & 2047;
                        const size_t idx = (((size_t)((b * HH + h) * DKK + dkk)) * SS) + sq;
                        __nv_bfloat16 hv = __float2bfloat16_rn(f);
                        g_Vthi[idx] = hv;
                        g_Vtlo[idx] = __float2bfloat16_rn(f - __bfloat162float(hv));
                    }
                } else {
                    __nv_bfloat16* Dh = (mode == 0) ? g_Pqhi : g_Pkhi;
                    __nv_bfloat16* Dl = (mode == 0) ? g_Pqlo : g_Pklo;
                    uint32_t hi, lo;
                    {
                        const int b = rA >> 11, sq = rA & 2047;
                        const size_t idx = (((size_t)(b * HH + h)) * SS + sq) * DKK + dk;
                        split2(f0, f1, hi, lo);
                        *(uint32_t*)&Dh[idx] = hi;
                        *(uint32_t*)&Dl[idx] = lo;
                    }
                    {
                        const int r2 = rA + 8;
                        const int b = r2 >> 11, sq = r2 & 2047;
                        const size_t idx = (((size_t)(b * HH + h)) * SS + sq) * DKK + dk;
                        split2(f2, f3, hi, lo);
                        *(uint32_t*)&Dh[idx] = hi;
                        *(uint32_t*)&Dl[idx] = lo;
                    }
                }
            }
        }
    }
}

// ---------------------------------------------------------------------------
// Tensor-core flash attention (causal), 3-term bf16 split on QK^T and PV.
// R14: CTA = 64 q-rows, 4 warps (128 threads). smem 80KB -> 2 CTAs/SM with
// NO register cap; two independent CTAs interleave softmax/MMA phases.
// grid (S/64, B*H) heavy-first. K-tiles of 64 keys, double buffer.
// Output -> g_Ahi[0]/g_Alo[0]  (A operand of the Wo GEMM).
// ---------------------------------------------------------------------------
#define AS_QHI   0
#define AS_QLO   8192
#define AS_STG   16384
#define AS_STGSZ 32768          // KHI 0 | KLO 8192 | VHI 16384 | VLO 24576
#define ATTN_SMEM (AS_STG + 2*AS_STGSZ)   // 81920

#define C_SCALE 0.180336880f    // 0.125 * log2(e)

// 128B rows (64 bf16): XOR swizzle over 8 units (conflict-free)
static __device__ __forceinline__ uint32_t sw128(int row, int u) {
    return (uint32_t)(row * 128 + ((u ^ (row & 7)) << 4));
}

__global__ __launch_bounds__(128)
void attn_tc()
{
    extern __shared__ char sm[];
    const uint32_t sb = smem_u32(sm);
    const int tid  = threadIdx.x;
    const int warp = tid >> 5;            // 0..3
    const int lane = tid & 31;
    const int lrow = lane & 15, lhalf = lane >> 4;
    const int g = lane >> 2,  t4 = lane & 3;
    // Heavy-first (LPT): large q0 CTAs scheduled first.
    const int q0 = (gridDim.x - 1 - blockIdx.x) * 64;
    const int bh = blockIdx.y;

    const __nv_bfloat16* __restrict__ Qhi = g_Pqhi + (size_t)bh * SS * DKK;
    const __nv_bfloat16* __restrict__ Qlo = g_Pqlo + (size_t)bh * SS * DKK;
    const __nv_bfloat16* __restrict__ Khi = g_Pkhi + (size_t)bh * SS * DKK;
    const __nv_bfloat16* __restrict__ Klo = g_Pklo + (size_t)bh * SS * DKK;
    const __nv_bfloat16* __restrict__ Vth = g_Vthi + (size_t)bh * DKK * SS;
    const __nv_bfloat16* __restrict__ Vtl = g_Vtlo + (size_t)bh * DKK * SS;

    // Q load (once): 64 rows x 8 units, hi+lo  (512 units / 128 thr = 4 iters)
    #pragma unroll
    for (int i = 0; i < 4; i++) {
        const int un = tid + i * 128;
        const int r = un >> 3, u = un & 7;
        const size_t go = (size_t)(q0 + r) * DKK + u * 8;
        CP_ASYNC16(sb + AS_QHI + sw128(r, u), Qhi + go);
        CP_ASYNC16(sb + AS_QLO + sw128(r, u), Qlo + go);
    }

    auto cpKV = [&](int t) {
        const int k0 = t * 64;
        const uint32_t st = sb + AS_STG + (uint32_t)(t & 1) * AS_STGSZ;
        #pragma unroll
        for (int i = 0; i < 4; i++) {
            const int un = tid + i * 128;     // 512 units (64 rows x 8)
            const int r = un >> 3, u = un & 7;
            CP_ASYNC16(st + 0     + sw128(r, u), Khi + (size_t)(k0 + r) * DKK + u * 8);
            CP_ASYNC16(st + 8192  + sw128(r, u), Klo + (size_t)(k0 + r) * DKK + u * 8);
            CP_ASYNC16(st + 16384 + sw128(r, u), Vth + (size_t)r * SS + k0 + u * 8);
            CP_ASYNC16(st + 24576 + sw128(r, u), Vtl + (size_t)r * SS + k0 + u * 8);
        }
    };

    float O[8][4];
    #pragma unroll
    for (int nf = 0; nf < 8; nf++)
        #pragma unroll
        for (int r = 0; r < 4; r++) O[nf][r] = 0.0f;
    float m0 = -1e30f, m8 = -1e30f, l0v = 0.0f, l8v = 0.0f;

    const int nkt = q0 / 64 + 1;          // tiles 0..q0/64 (diag = last)

    cpKV(0);
    CP_COMMIT();

    for (int t = 0; t < nkt; t++) {
        if (t + 1 < nkt) { cpKV(t + 1); CP_COMMIT(); CP_WAIT1(); }
        else             { CP_WAIT0(); }
        __syncthreads();

        const uint32_t st = sb + AS_STG + (uint32_t)(t & 1) * AS_STGSZ;

        // ---- S = Q K^T (3-term) ----
        float sc[8][4];
        #pragma unroll
        for (int nf = 0; nf < 8; nf++)
            #pragma unroll
            for (int r = 0; r < 4; r++) sc[nf][r] = 0.0f;

        #pragma unroll
        for (int s = 0; s < 4; s++) {
            uint32_t aH[4], aL[4];
            const uint32_t qa = sb + AS_QHI + sw128(warp * 16 + lrow, 2 * s + lhalf);
            LDSM_X4(aH, qa);
            LDSM_X4(aL, qa + (AS_QLO - AS_QHI));
            uint32_t bH[4][4], bL[4][4];
            #pragma unroll
            for (int kg = 0; kg < 4; kg++) {
                const uint32_t ka = st + sw128(kg * 16 + lrow, 2 * s + lhalf);
                LDSM_X4(bH[kg], ka);
                LDSM_X4(bL[kg], ka + 8192);
            }
            #pragma unroll
            for (int nf = 0; nf < 8; nf++) {
                const int kg = nf >> 1, h = nf & 1;
                MMA16816(sc[nf], aH, bH[kg][h], bH[kg][h + 2]);
                MMA16816(sc[nf], aH, bL[kg][h], bL[kg][h + 2]);
                MMA16816(sc[nf], aL, bH[kg][h], bH[kg][h + 2]);
            }
        }

        // ---- causal mask (only the diagonal tile t == q0/64) ----
        const int k0 = t * 64;
        if (k0 + 63 > q0) {
            const int r0g = q0 + warp * 16 + g;
            const int r8g = r0g + 8;
            #pragma unroll
            for (int nf = 0; nf < 8; nf++) {
                const int c0 = k0 + nf * 8 + t4 * 2;
                if (c0     > r0g) sc[nf][0] = -1e30f;
                if (c0 + 1 > r0g) sc[nf][1] = -1e30f;
                if (c0     > r8g) sc[nf][2] = -1e30f;
                if (c0 + 1 > r8g) sc[nf][3] = -1e30f;
            }
        }

        // ---- online softmax (rows g and g+8; reduce over 4 lanes) ----
        float mx0 = -1e30f, mx8 = -1e30f;
        #pragma unroll
        for (int nf = 0; nf < 8; nf++) {
            mx0 = fmaxf(mx0, fmaxf(sc[nf][0], sc[nf][1]));
            mx8 = fmaxf(mx8, fmaxf(sc[nf][2], sc[nf][3]));
        }
        mx0 = fmaxf(mx0, __shfl_xor_sync(0xffffffffu, mx0, 1));
        mx0 = fmaxf(mx0, __shfl_xor_sync(0xffffffffu, mx0, 2));
        mx8 = fmaxf(mx8, __shfl_xor_sync(0xffffffffu, mx8, 1));
        mx8 = fmaxf(mx8, __shfl_xor_sync(0xffffffffu, mx8, 2));

        const float mn0 = fmaxf(m0, mx0), mn8 = fmaxf(m8, mx8);
        const float al0 = exp2f((m0 - mn0) * C_SCALE);
        const float al8 = exp2f((m8 - mn8) * C_SCALE);

        float rs0 = 0.0f, rs8 = 0.0f;
        #pragma unroll
        for (int nf = 0; nf < 8; nf++) {
            sc[nf][0] = exp2f((sc[nf][0] - mn0) * C_SCALE);
            sc[nf][1] = exp2f((sc[nf][1] - mn0) * C_SCALE);
            sc[nf][2] = exp2f((sc[nf][2] - mn8) * C_SCALE);
            sc[nf][3] = exp2f((sc[nf][3] - mn8) * C_SCALE);
            rs0 += sc[nf][0] + sc[nf][1];
            rs8 += sc[nf][2] + sc[nf][3];
        }
        rs0 += __shfl_xor_sync(0xffffffffu, rs0, 1);
        rs0 += __shfl_xor_sync(0xffffffffu, rs0, 2);
        rs8 += __shfl_xor_sync(0xffffffffu, rs8, 1);
        rs8 += __shfl_xor_sync(0xffffffffu, rs8, 2);

        l0v = l0v * al0 + rs0;
        l8v = l8v * al8 + rs8;
        m0 = mn0; m8 = mn8;

        #pragma unroll
        for (int nf = 0; nf < 8; nf++) {
            O[nf][0] *= al0; O[nf][1] *= al0;
            O[nf][2] *= al8; O[nf][3] *= al8;
        }

        // ---- pack P into A-operand frags (hi/lo) ----
        uint32_t aPh[4][4], aPl[4][4];
        #pragma unroll
        for (int s = 0; s < 4; s++) {
            split2(sc[2*s][0],   sc[2*s][1],   aPh[s][0], aPl[s][0]);
            split2(sc[2*s][2],   sc[2*s][3],   aPh[s][1], aPl[s][1]);
            split2(sc[2*s+1][0], sc[2*s+1][1], aPh[s][2], aPl[s][2]);
            split2(sc[2*s+1][2], sc[2*s+1][3], aPh[s][3], aPl[s][3]);
        }

        // ---- O += P V (3-term) ----
        #pragma unroll
        for (int s = 0; s < 4; s++) {
            uint32_t vH[4][4], vL[4][4];
            #pragma unroll
            for (int vg = 0; vg < 4; vg++) {
                const uint32_t va = st + 16384 + sw128(vg * 16 + lrow, 2 * s + lhalf);
                LDSM_X4(vH[vg], va);
                LDSM_X4(vL[vg], va + 8192);
            }
            #pragma unroll
            for (int nf = 0; nf < 8; nf++) {
                const int vg = nf >> 1, h = nf & 1;
                MMA16816(O[nf], aPh[s], vH[vg][h], vH[vg][h + 2]);
                MMA16816(O[nf], aPh[s], vL[vg][h], vL[vg][h + 2]);
                MMA16816(O[nf], aPl[s], vH[vg][h], vH[vg][h + 2]);
            }
        }
        __syncthreads();
    }

    // ---- epilogue: O/l -> bf16 hi/lo into A slot 0 ----
    const float i0 = 1.0f / l0v, i8 = 1.0f / l8v;
    const int b = bh >> 4, h = bh & 15;
    const int s0 = q0 + warp * 16 + g;
    #pragma unroll
    for (int nf = 0; nf < 8; nf++) {
        const int n = h * 64 + nf * 8 + t4 * 2;
        uint32_t hi, lo;
        split2(O[nf][0] * i0, O[nf][1] * i0, hi, lo);
        size_t idx = ((size_t)b * SS + s0) * DD + n;
        *(uint32_t*)&g_Ahi[0][idx] = hi;
        *(uint32_t*)&g_Alo[0][idx] = lo;
        split2(O[nf][2] * i8, O[nf][3] * i8, hi, lo);
        idx = ((size_t)b * SS + s0 + 8) * DD + n;
        *(uint32_t*)&g_Ahi[0][idx] = hi;
        *(uint32_t*)&g_Alo[0][idx] = lo;
    }
}

// ---------------------------------------------------------------------------
// Launch
// ---------------------------------------------------------------------------
extern "C" void kernel_launch(void* const* d_in, const int* in_sizes, int n_in,
                              void* d_out, int out_size)
{
    const float* q  = (const float*)d_in[0];
    const float* k  = (const float*)d_in[1];
    const float* v  = (const float*)d_in[2];
    // d_in[3] = causal mask (structure known, not read)
    const float* Wq = (const float*)d_in[4];
    const float* bq = (const float*)d_in[5];
    const float* Wk = (const float*)d_in[6];
    const float* bk = (const float*)d_in[7];
    const float* Wv = (const float*)d_in[8];
    const float* bv = (const float*)d_in[9];
    const float* Wo = (const float*)d_in[10];
    const float* bo = (const float*)d_in[11];
    float* out = (float*)d_out;

    cudaFuncSetAttribute(attn_tc,
                         cudaFuncAttributeMaxDynamicSharedMemorySize, ATTN_SMEM);
    cudaFuncSetAttribute(mma_gemm_all,
                         cudaFuncAttributeMaxDynamicSharedMemorySize, G_SMEM);

    dim3 cgrid((MM * DD / 4) / 256, 3);               // (4096, 3)
    dim3 wgrid(DD / 32, DD / 32, 4);                  // (32, 32, 4)
    dim3 wblk(32, 8);

    convA_kernel<<<cgrid, 256>>>(q, k, v);            // q,k,v -> slots 0,1,2
    convW_kernel<<<wgrid, wblk>>>(Wq, Wk, Wv, Wo);    // all 4 W^T splits

    dim3 gqkv(MM / GBM, DD / GBN, 3);                 // (32, 8, 3) merged QKV
    mma_gemm_all<<<gqkv, 256, G_SMEM>>>(bq, bk, bv, bo, nullptr, 0);

    dim3 agrid(SS / 64, BB * HH);                     // (32, 32) 64-row CTAs
    attn_tc<<<agrid, 128, ATTN_SMEM>>>();

    dim3 gout(MM / GBM, DD / GBN, 1);                 // (32, 8, 1) Wo
    mma_gemm_all<<<gout, 256, G_SMEM>>>(bq, bk, bv, bo, out, 3);
}